// round 1
// baseline (speedup 1.0000x reference)
#include <cuda_runtime.h>

#define B_    128
#define NT_   512
#define NC_   512
#define EMB_  256
#define D_    60
#define DP_   64   // padded head dim

// ---------------- scratch (device globals; no allocation allowed) ----------------
__device__ float g_q  [B_*NT_*DP_];
__device__ float g_k  [B_*NC_*DP_];
__device__ float g_v  [B_*NC_*DP_];
__device__ float g_s  [B_*NT_*DP_];   // attention output (pre R-proj), padded to 64
__device__ float g_rqn[B_*NT_];
__device__ float g_rkn[B_*NC_];

// =================================================================================
// Projection kernels: Y[128 rows][60] = gather(vec, items) @ W^T + b  (+ 1/norm)
// Block: 256 threads as (16,16). Thread computes 8 rows x 4 outs.
// Smem: Xs[128][257], Ws[64][257]  (odd stride -> conflict-light scalar LDS)
// =================================================================================

__device__ __forceinline__ void load_W_smem(float* Ws, const float* __restrict__ W) {
    int tid = threadIdx.y * 16 + threadIdx.x;
    for (int idx = tid; idx < D_ * EMB_; idx += 256) {
        int o = idx >> 8, e = idx & 255;
        Ws[o * 257 + e] = W[idx];
    }
    // zero-pad outs 60..63 so padded lanes produce exact zeros
    for (int idx = tid; idx < (DP_ - D_) * EMB_; idx += 256) {
        int o = D_ + (idx >> 8), e = idx & 255;
        Ws[o * 257 + e] = 0.f;
    }
}

__device__ __forceinline__ void gather_X_smem(float* Xs, const int* items,
                                              const float* __restrict__ vec) {
    int tid  = threadIdx.y * 16 + threadIdx.x;
    int rsub = tid >> 6, l64 = tid & 63;
    for (int rr = 0; rr < 128; rr += 4) {
        int r = rr + rsub;
        float4 xv = ((const float4*)(vec + (size_t)items[r] * EMB_))[l64];
        float* dst = Xs + r * 257 + l64 * 4;
        dst[0] = xv.x; dst[1] = xv.y; dst[2] = xv.z; dst[3] = xv.w;
    }
}

__device__ __forceinline__ void proj_tile(const float* Xs, const float* Ws,
                                          const float* __restrict__ bias,
                                          float* outBase, float* rnormBase,
                                          bool doNorm) {
    int tx = threadIdx.x, ty = threadIdx.y;
    float acc[8][4];
#pragma unroll
    for (int i = 0; i < 8; i++)
#pragma unroll
        for (int m = 0; m < 4; m++) acc[i][m] = 0.f;

#pragma unroll 4
    for (int e = 0; e < EMB_; e++) {
        float wv[4];
#pragma unroll
        for (int m = 0; m < 4; m++) wv[m] = Ws[(tx * 4 + m) * 257 + e];
#pragma unroll
        for (int i = 0; i < 8; i++) {
            float xv = Xs[(ty * 8 + i) * 257 + e];
#pragma unroll
            for (int m = 0; m < 4; m++) acc[i][m] += xv * wv[m];
        }
    }
    float bb[4];
#pragma unroll
    for (int m = 0; m < 4; m++) {
        int o = tx * 4 + m;
        bb[m] = (o < D_) ? bias[o] : 0.f;
    }
#pragma unroll
    for (int i = 0; i < 8; i++) {
        float4 f4;
        f4.x = acc[i][0] + bb[0];
        f4.y = acc[i][1] + bb[1];
        f4.z = acc[i][2] + bb[2];
        f4.w = acc[i][3] + bb[3];
        int r = ty * 8 + i;
        ((float4*)(outBase + (size_t)r * DP_))[tx] = f4;
        if (doNorm) {
            float ss = f4.x * f4.x + f4.y * f4.y + f4.z * f4.z + f4.w * f4.w;
#pragma unroll
            for (int off = 8; off >= 1; off >>= 1)
                ss += __shfl_xor_sync(0xffffffffu, ss, off, 16);
            if (tx == 0) rnormBase[r] = rsqrtf(ss);
        }
    }
}

__global__ void __launch_bounds__(256)
proj_q_kernel(const int* __restrict__ items_g, const float* __restrict__ vec,
              const float* __restrict__ W, const float* __restrict__ bias) {
    extern __shared__ float sm[];
    float* Xs = sm;                // 128*257
    float* Ws = sm + 128 * 257;    // 64*257
    __shared__ int items[128];
    int b = blockIdx.x >> 2, r0 = (blockIdx.x & 3) * 128;
    int tid = threadIdx.y * 16 + threadIdx.x;
    if (tid < 128) items[tid] = items_g[b * NT_ + r0 + tid];
    load_W_smem(Ws, W);
    __syncthreads();
    gather_X_smem(Xs, items, vec);
    __syncthreads();
    proj_tile(Xs, Ws, bias, g_q + ((size_t)b * NT_ + r0) * DP_, g_rqn + b * NT_ + r0, true);
}

__global__ void __launch_bounds__(256)
proj_kv_kernel(const int* __restrict__ items_g, const float* __restrict__ vec,
               const float* __restrict__ Wk, const float* __restrict__ bk,
               const float* __restrict__ Wv, const float* __restrict__ bv) {
    extern __shared__ float sm[];
    float* Xs = sm;
    float* Ws = sm + 128 * 257;
    __shared__ int items[128];
    int b = blockIdx.x >> 2, r0 = (blockIdx.x & 3) * 128;
    int tid = threadIdx.y * 16 + threadIdx.x;
    if (tid < 128) items[tid] = items_g[b * NC_ + r0 + tid];
    load_W_smem(Ws, Wk);
    __syncthreads();
    gather_X_smem(Xs, items, vec);
    __syncthreads();
    proj_tile(Xs, Ws, bk, g_k + ((size_t)b * NC_ + r0) * DP_, g_rkn + b * NC_ + r0, true);
    __syncthreads();
    load_W_smem(Ws, Wv);
    __syncthreads();
    proj_tile(Xs, Ws, bv, g_v + ((size_t)b * NC_ + r0) * DP_, nullptr, false);
}

// =================================================================================
// Attention: per block = (b, 64 t-rows). Flash-style online softmax over 8 c-tiles
// of 64. Score phase: thread tile 4t x 4c. PV phase: thread tile 4t x 4d.
// =================================================================================

__global__ void __launch_bounds__(256)
attn_kernel(const float* __restrict__ pos_bias) {
    extern __shared__ float sm[];
    float* Qs    = sm;                 // 64*65
    float* Ks    = Qs + 64 * 65;
    float* Vs    = Ks + 64 * 65;
    float* Ps    = Vs + 64 * 65;
    float* rqn_s = Ps + 64 * 65;       // 64
    float* rkn_s = rqn_s + 64;
    float* pb_s  = rkn_s + 64;
    float* m_s   = pb_s + 64;
    float* l_s   = m_s + 64;
    float* al_s  = l_s + 64;

    int b  = blockIdx.x >> 3;
    int t0 = (blockIdx.x & 7) * 64;
    int tx = threadIdx.x, ty = threadIdx.y;
    int tid = ty * 16 + tx;

    // load Q tile
#pragma unroll
    for (int it = 0; it < 4; it++) {
        int r = it * 16 + (tid >> 4), f4 = tid & 15;
        float4 v = ((const float4*)(g_q + ((size_t)(b * NT_ + t0 + r)) * DP_))[f4];
        float* dst = Qs + r * 65 + f4 * 4;
        dst[0] = v.x; dst[1] = v.y; dst[2] = v.z; dst[3] = v.w;
    }
    if (tid < 64) {
        rqn_s[tid] = g_rqn[b * NT_ + t0 + tid];
        m_s[tid]   = -1e30f;
        l_s[tid]   = 0.f;
    }

    float oacc[4][4];
#pragma unroll
    for (int i = 0; i < 4; i++)
#pragma unroll
        for (int m = 0; m < 4; m++) oacc[i][m] = 0.f;

    for (int ci = 0; ci < 8; ci++) {
        int c0 = ci * 64;
        __syncthreads();   // previous PV done before K/V overwrite
#pragma unroll
        for (int it = 0; it < 4; it++) {
            int r = it * 16 + (tid >> 4), f4 = tid & 15;
            float4 kv = ((const float4*)(g_k + ((size_t)(b * NC_ + c0 + r)) * DP_))[f4];
            float* kd = Ks + r * 65 + f4 * 4;
            kd[0] = kv.x; kd[1] = kv.y; kd[2] = kv.z; kd[3] = kv.w;
            float4 vv = ((const float4*)(g_v + ((size_t)(b * NC_ + c0 + r)) * DP_))[f4];
            float* vd = Vs + r * 65 + f4 * 4;
            vd[0] = vv.x; vd[1] = vv.y; vd[2] = vv.z; vd[3] = vv.w;
        }
        if (tid < 64) {
            rkn_s[tid] = g_rkn[b * NC_ + c0 + tid];
            pb_s[tid]  = pos_bias[c0 + tid];
        }
        __syncthreads();

        // ---- scores: s[4t][4c] ----
        float s[4][4];
#pragma unroll
        for (int i = 0; i < 4; i++)
#pragma unroll
            for (int j = 0; j < 4; j++) s[i][j] = 0.f;
#pragma unroll 4
        for (int e = 0; e < D_; e++) {
            float qv[4], kv[4];
#pragma unroll
            for (int i = 0; i < 4; i++) qv[i] = Qs[(ty * 4 + i) * 65 + e];
#pragma unroll
            for (int j = 0; j < 4; j++) kv[j] = Ks[(tx * 4 + j) * 65 + e];
#pragma unroll
            for (int i = 0; i < 4; i++)
#pragma unroll
                for (int j = 0; j < 4; j++) s[i][j] += qv[i] * kv[j];
        }
        float rq[4], rk[4], pb[4];
#pragma unroll
        for (int i = 0; i < 4; i++) rq[i] = rqn_s[ty * 4 + i];
#pragma unroll
        for (int j = 0; j < 4; j++) { rk[j] = rkn_s[tx * 4 + j]; pb[j] = pb_s[tx * 4 + j]; }
#pragma unroll
        for (int i = 0; i < 4; i++)
#pragma unroll
            for (int j = 0; j < 4; j++)
                s[i][j] = s[i][j] * fminf(rq[i] * rk[j], 1e6f) + pb[j];

        // ---- online softmax stats (row group = 16 tx lanes, same warp half) ----
#pragma unroll
        for (int i = 0; i < 4; i++) {
            float mx = fmaxf(fmaxf(s[i][0], s[i][1]), fmaxf(s[i][2], s[i][3]));
#pragma unroll
            for (int off = 8; off >= 1; off >>= 1)
                mx = fmaxf(mx, __shfl_xor_sync(0xffffffffu, mx, off, 16));
            float mold = m_s[ty * 4 + i];
            float mnew = fmaxf(mold, mx);
            float alpha = __expf(mold - mnew);
            float sum = 0.f;
#pragma unroll
            for (int j = 0; j < 4; j++) {
                s[i][j] = __expf(s[i][j] - mnew);
                sum += s[i][j];
            }
#pragma unroll
            for (int off = 8; off >= 1; off >>= 1)
                sum += __shfl_xor_sync(0xffffffffu, sum, off, 16);
            if (tx == 0) {
                m_s[ty * 4 + i]  = mnew;
                l_s[ty * 4 + i]  = l_s[ty * 4 + i] * alpha + sum;
                al_s[ty * 4 + i] = alpha;
            }
        }
#pragma unroll
        for (int i = 0; i < 4; i++)
#pragma unroll
            for (int j = 0; j < 4; j++)
                Ps[(ty * 4 + i) * 65 + tx * 4 + j] = s[i][j];
        __syncthreads();

        // ---- PV: thread tile 4t x 4d ----
        float al[4];
#pragma unroll
        for (int i = 0; i < 4; i++) al[i] = al_s[ty * 4 + i];
#pragma unroll
        for (int i = 0; i < 4; i++)
#pragma unroll
            for (int m = 0; m < 4; m++) oacc[i][m] *= al[i];
#pragma unroll 4
        for (int c = 0; c < 64; c++) {
            float vv[4];
#pragma unroll
            for (int m = 0; m < 4; m++) vv[m] = Vs[c * 65 + tx * 4 + m];
#pragma unroll
            for (int i = 0; i < 4; i++) {
                float p = Ps[(ty * 4 + i) * 65 + c];
#pragma unroll
                for (int m = 0; m < 4; m++) oacc[i][m] += p * vv[m];
            }
        }
    }

    // finalize (l_s written by tx==0 of same warp; last cross-thread write crossed a sync)
#pragma unroll
    for (int i = 0; i < 4; i++) {
        float linv = 1.f / l_s[ty * 4 + i];
        float4 o4;
        o4.x = oacc[i][0] * linv; o4.y = oacc[i][1] * linv;
        o4.z = oacc[i][2] * linv; o4.w = oacc[i][3] * linv;
        ((float4*)(g_s + ((size_t)(b * NT_ + t0 + ty * 4 + i)) * DP_))[tx] = o4;
    }
}

// =================================================================================
// Output projection: out[row][256] = g_s[row][0:60] @ R_w^T + R_b
// Block: 128 rows x 64 outs; thread 8 rows x 4 outs. K = 60.
// =================================================================================

__global__ void __launch_bounds__(256)
rproj_kernel(const float* __restrict__ Rw, const float* __restrict__ Rb,
             float* __restrict__ out) {
    extern __shared__ float sm[];
    float* Xs = sm;               // 128*65
    float* Ws = sm + 128 * 65;    // 64*65
    int rowblk = blockIdx.x >> 2;
    int oc = (blockIdx.x & 3) * 64;
    int row0 = rowblk * 128;
    int tx = threadIdx.x, ty = threadIdx.y;
    int tid = ty * 16 + tx;

#pragma unroll
    for (int it = 0; it < 8; it++) {
        int r = it * 16 + (tid >> 4), f4 = tid & 15;
        float4 v = ((const float4*)(g_s + ((size_t)(row0 + r)) * DP_))[f4];
        float* dst = Xs + r * 65 + f4 * 4;
        dst[0] = v.x; dst[1] = v.y; dst[2] = v.z; dst[3] = v.w;
    }
    for (int idx = tid; idx < 64 * D_; idx += 256) {
        int o = idx / D_, e = idx % D_;
        Ws[o * 65 + e] = Rw[(size_t)(oc + o) * D_ + e];
    }
    __syncthreads();

    float acc[8][4];
#pragma unroll
    for (int i = 0; i < 8; i++)
#pragma unroll
        for (int m = 0; m < 4; m++) acc[i][m] = 0.f;
#pragma unroll 4
    for (int e = 0; e < D_; e++) {
        float wv[4];
#pragma unroll
        for (int m = 0; m < 4; m++) wv[m] = Ws[(tx * 4 + m) * 65 + e];
#pragma unroll
        for (int i = 0; i < 8; i++) {
            float xv = Xs[(ty * 8 + i) * 65 + e];
#pragma unroll
            for (int m = 0; m < 4; m++) acc[i][m] += xv * wv[m];
        }
    }
    float bb[4];
#pragma unroll
    for (int m = 0; m < 4; m++) bb[m] = Rb[oc + tx * 4 + m];
#pragma unroll
    for (int i = 0; i < 8; i++) {
        int r = ty * 8 + i;
        float4 o4;
        o4.x = acc[i][0] + bb[0]; o4.y = acc[i][1] + bb[1];
        o4.z = acc[i][2] + bb[2]; o4.w = acc[i][3] + bb[3];
        ((float4*)(out + (size_t)(row0 + r) * EMB_ + oc))[tx] = o4;
    }
}

// =================================================================================
// launch
// =================================================================================

extern "C" void kernel_launch(void* const* d_in, const int* in_sizes, int n_in,
                              void* d_out, int out_size) {
    const int*   titems   = (const int*)  d_in[0];
    const int*   citems   = (const int*)  d_in[1];
    const float* tvec     = (const float*)d_in[2];
    const float* cvec     = (const float*)d_in[3];
    const float* At_w     = (const float*)d_in[4];
    const float* At_b     = (const float*)d_in[5];
    const float* Ac_w     = (const float*)d_in[6];
    const float* Ac_b     = (const float*)d_in[7];
    const float* Bc_w     = (const float*)d_in[8];
    const float* Bc_b     = (const float*)d_in[9];
    const float* pos_bias = (const float*)d_in[10];
    const float* R_w      = (const float*)d_in[11];
    const float* R_b      = (const float*)d_in[12];
    float* out = (float*)d_out;

    const int SMEM_PROJ = (128 * 257 + 64 * 257) * 4;   // 197376
    const int SMEM_ATTN = (4 * 64 * 65 + 6 * 64) * 4;   // 68096
    const int SMEM_R    = (128 * 65 + 64 * 65) * 4;     // 49920

    cudaFuncSetAttribute((const void*)proj_q_kernel,
                         cudaFuncAttributeMaxDynamicSharedMemorySize, SMEM_PROJ);
    cudaFuncSetAttribute((const void*)proj_kv_kernel,
                         cudaFuncAttributeMaxDynamicSharedMemorySize, SMEM_PROJ);
    cudaFuncSetAttribute((const void*)attn_kernel,
                         cudaFuncAttributeMaxDynamicSharedMemorySize, SMEM_ATTN);
    cudaFuncSetAttribute((const void*)rproj_kernel,
                         cudaFuncAttributeMaxDynamicSharedMemorySize, SMEM_R);

    dim3 blk(16, 16);
    proj_q_kernel <<<512, blk, SMEM_PROJ>>>(titems, tvec, At_w, At_b);
    proj_kv_kernel<<<512, blk, SMEM_PROJ>>>(citems, cvec, Ac_w, Ac_b, Bc_w, Bc_b);
    attn_kernel   <<<1024, blk, SMEM_ATTN>>>(pos_bias);
    rproj_kernel  <<<2048, blk, SMEM_R>>>(R_w, R_b, out);
}

// round 3
// speedup vs baseline: 1.2274x; 1.2274x over previous
#include <cuda_runtime.h>
#include <cstdint>

#define B_    128
#define NT_   512
#define NC_   512
#define EMB_  256
#define D_    60
#define DP_   64
#define S68   68   // smem row stride (floats): 68*r mod 32 = 4r -> conflict-free frags

// ---------------- scratch (device globals; no allocation allowed) ----------------
__device__ float g_q  [B_*NT_*DP_];
__device__ float g_k  [B_*NC_*DP_];
__device__ float g_v  [B_*NC_*DP_];
__device__ float g_s  [B_*NT_*DP_];
__device__ float g_rqn[B_*NT_];
__device__ float g_rkn[B_*NC_];

// ---------------- tf32 helpers ----------------
__device__ __forceinline__ uint32_t f2tf(float x) {
    uint32_t u;
    asm("cvt.rna.tf32.f32 %0, %1;" : "=r"(u) : "f"(x));
    return u;
}
// store hi/lo split of x at H[idx], L[idx]
__device__ __forceinline__ void split_store(float* H, float* L, int idx, float x) {
    uint32_t h = f2tf(x);
    float hf = __uint_as_float(h);
    H[idx] = hf;
    L[idx] = __uint_as_float(f2tf(x - hf));
}
__device__ __forceinline__ void mma8(float c[4], uint32_t a0, uint32_t a1,
                                     uint32_t a2, uint32_t a3,
                                     uint32_t b0, uint32_t b1) {
    asm volatile(
        "mma.sync.aligned.m16n8k8.row.col.f32.tf32.tf32.f32 "
        "{%0,%1,%2,%3},{%4,%5,%6,%7},{%8,%9},{%0,%1,%2,%3};"
        : "+f"(c[0]), "+f"(c[1]), "+f"(c[2]), "+f"(c[3])
        : "r"(a0), "r"(a1), "r"(a2), "r"(a3), "r"(b0), "r"(b1));
}
#define LD_A(H, L, base0, base1, k)                                   \
    uint32_t ah0 = __float_as_uint((H)[(base0) + (k) + t]);           \
    uint32_t ah1 = __float_as_uint((H)[(base1) + (k) + t]);           \
    uint32_t ah2 = __float_as_uint((H)[(base0) + (k) + t + 4]);       \
    uint32_t ah3 = __float_as_uint((H)[(base1) + (k) + t + 4]);       \
    uint32_t al0 = __float_as_uint((L)[(base0) + (k) + t]);           \
    uint32_t al1 = __float_as_uint((L)[(base1) + (k) + t]);           \
    uint32_t al2 = __float_as_uint((L)[(base0) + (k) + t + 4]);       \
    uint32_t al3 = __float_as_uint((L)[(base1) + (k) + t + 4]);

#define MMA3(acc, BH, BL, off)                                        \
    {                                                                 \
        uint32_t bh0 = __float_as_uint((BH)[(off) + t]);              \
        uint32_t bh1 = __float_as_uint((BH)[(off) + t + 4]);          \
        uint32_t bl0 = __float_as_uint((BL)[(off) + t]);              \
        uint32_t bl1 = __float_as_uint((BL)[(off) + t + 4]);          \
        mma8(acc, ah0, ah1, ah2, ah3, bh0, bh1);                      \
        mma8(acc, ah0, ah1, ah2, ah3, bl0, bl1);                      \
        mma8(acc, al0, al1, al2, al3, bh0, bh1);                      \
    }

// =================================================================================
// proj_q: q[128rows][64] = gather(tvec,items) @ At_w^T + b, plus 1/|q| row norms.
// Block 256thr = 8 warps, warp = 16 rows. K=256 chunked by 64.
// =================================================================================
__global__ void __launch_bounds__(256)
proj_q_kernel(const int* __restrict__ items_g, const float* __restrict__ vec,
              const float* __restrict__ W, const float* __restrict__ bias) {
    extern __shared__ float sm[];
    float* Xh = sm;                    // 128*68
    float* Xl = Xh + 128 * S68;
    float* Wh = Xl + 128 * S68;        // 64*68
    float* Wl = Wh + 64 * S68;
    __shared__ int items[128];

    int b = blockIdx.x >> 2, r0 = (blockIdx.x & 3) * 128;
    int tid = threadIdx.x, warp = tid >> 5, lane = tid & 31, g = lane >> 2, t = lane & 3;
    if (tid < 128) items[tid] = items_g[b * NT_ + r0 + tid];
    __syncthreads();

    float acc[8][4];
#pragma unroll
    for (int n = 0; n < 8; n++)
#pragma unroll
        for (int m = 0; m < 4; m++) acc[n][m] = 0.f;

    int rA = warp * 16 + g;
    for (int k0 = 0; k0 < EMB_; k0 += 64) {
        __syncthreads();
        for (int i = tid; i < 128 * 16; i += 256) {
            int r = i >> 4, c4 = (i & 15) * 4;
            float4 v = *(const float4*)(vec + (size_t)items[r] * EMB_ + k0 + c4);
            int bix = r * S68 + c4;
            split_store(Xh, Xl, bix,     v.x); split_store(Xh, Xl, bix + 1, v.y);
            split_store(Xh, Xl, bix + 2, v.z); split_store(Xh, Xl, bix + 3, v.w);
        }
        for (int i = tid; i < 64 * 16; i += 256) {
            int o = i >> 4, c4 = (i & 15) * 4;
            float4 v = make_float4(0.f, 0.f, 0.f, 0.f);
            if (o < D_) v = *(const float4*)(W + (size_t)o * EMB_ + k0 + c4);
            int bix = o * S68 + c4;
            split_store(Wh, Wl, bix,     v.x); split_store(Wh, Wl, bix + 1, v.y);
            split_store(Wh, Wl, bix + 2, v.z); split_store(Wh, Wl, bix + 3, v.w);
        }
        __syncthreads();
#pragma unroll 1
        for (int kk = 0; kk < 64; kk += 8) {
            LD_A(Xh, Xl, rA * S68, (rA + 8) * S68, kk);
#pragma unroll
            for (int n = 0; n < 8; n++)
                MMA3(acc[n], Wh, Wl, (n * 8 + g) * S68 + kk);
        }
    }
    // epilogue: bias, store, row norms
    float ss0 = 0.f, ss1 = 0.f;
    size_t rowg = (size_t)(b * NT_ + r0 + rA);
#pragma unroll
    for (int n = 0; n < 8; n++) {
        int col = n * 8 + 2 * t;
        float b0 = (col < D_) ? bias[col] : 0.f;
        float b1 = (col + 1 < D_) ? bias[col + 1] : 0.f;
        float v00 = acc[n][0] + b0, v01 = acc[n][1] + b1;
        float v10 = acc[n][2] + b0, v11 = acc[n][3] + b1;
        ss0 += v00 * v00 + v01 * v01;
        ss1 += v10 * v10 + v11 * v11;
        *(float2*)(g_q + rowg * DP_ + col)       = make_float2(v00, v01);
        *(float2*)(g_q + (rowg + 8) * DP_ + col) = make_float2(v10, v11);
    }
    ss0 += __shfl_xor_sync(0xffffffffu, ss0, 1, 4);
    ss0 += __shfl_xor_sync(0xffffffffu, ss0, 2, 4);
    ss1 += __shfl_xor_sync(0xffffffffu, ss1, 1, 4);
    ss1 += __shfl_xor_sync(0xffffffffu, ss1, 2, 4);
    if (t == 0) {
        g_rqn[rowg]     = rsqrtf(ss0);
        g_rqn[rowg + 8] = rsqrtf(ss1);
    }
}

// =================================================================================
// proj_kv: K and V projections sharing one gathered X; K also gets row norms.
// =================================================================================
__global__ void __launch_bounds__(256)
proj_kv_kernel(const int* __restrict__ items_g, const float* __restrict__ vec,
               const float* __restrict__ Wk, const float* __restrict__ bk,
               const float* __restrict__ Wv, const float* __restrict__ bv) {
    extern __shared__ float sm[];
    float* Xh  = sm;
    float* Xl  = Xh  + 128 * S68;
    float* Wkh = Xl  + 128 * S68;
    float* Wkl = Wkh + 64 * S68;
    float* Wvh = Wkl + 64 * S68;
    float* Wvl = Wvh + 64 * S68;
    __shared__ int items[128];

    int b = blockIdx.x >> 2, r0 = (blockIdx.x & 3) * 128;
    int tid = threadIdx.x, warp = tid >> 5, lane = tid & 31, g = lane >> 2, t = lane & 3;
    if (tid < 128) items[tid] = items_g[b * NC_ + r0 + tid];
    __syncthreads();

    float ak[8][4], av[8][4];
#pragma unroll
    for (int n = 0; n < 8; n++)
#pragma unroll
        for (int m = 0; m < 4; m++) { ak[n][m] = 0.f; av[n][m] = 0.f; }

    int rA = warp * 16 + g;
    for (int k0 = 0; k0 < EMB_; k0 += 64) {
        __syncthreads();
        for (int i = tid; i < 128 * 16; i += 256) {
            int r = i >> 4, c4 = (i & 15) * 4;
            float4 v = *(const float4*)(vec + (size_t)items[r] * EMB_ + k0 + c4);
            int bix = r * S68 + c4;
            split_store(Xh, Xl, bix,     v.x); split_store(Xh, Xl, bix + 1, v.y);
            split_store(Xh, Xl, bix + 2, v.z); split_store(Xh, Xl, bix + 3, v.w);
        }
        for (int i = tid; i < 64 * 16; i += 256) {
            int o = i >> 4, c4 = (i & 15) * 4;
            float4 vk = make_float4(0.f, 0.f, 0.f, 0.f), vv = vk;
            if (o < D_) {
                vk = *(const float4*)(Wk + (size_t)o * EMB_ + k0 + c4);
                vv = *(const float4*)(Wv + (size_t)o * EMB_ + k0 + c4);
            }
            int bix = o * S68 + c4;
            split_store(Wkh, Wkl, bix,     vk.x); split_store(Wkh, Wkl, bix + 1, vk.y);
            split_store(Wkh, Wkl, bix + 2, vk.z); split_store(Wkh, Wkl, bix + 3, vk.w);
            split_store(Wvh, Wvl, bix,     vv.x); split_store(Wvh, Wvl, bix + 1, vv.y);
            split_store(Wvh, Wvl, bix + 2, vv.z); split_store(Wvh, Wvl, bix + 3, vv.w);
        }
        __syncthreads();
#pragma unroll 1
        for (int kk = 0; kk < 64; kk += 8) {
            LD_A(Xh, Xl, rA * S68, (rA + 8) * S68, kk);
#pragma unroll
            for (int n = 0; n < 8; n++) {
                MMA3(ak[n], Wkh, Wkl, (n * 8 + g) * S68 + kk);
                MMA3(av[n], Wvh, Wvl, (n * 8 + g) * S68 + kk);
            }
        }
    }
    float ss0 = 0.f, ss1 = 0.f;
    size_t rowg = (size_t)(b * NC_ + r0 + rA);
#pragma unroll
    for (int n = 0; n < 8; n++) {
        int col = n * 8 + 2 * t;
        float bk0 = (col < D_) ? bk[col] : 0.f;
        float bk1 = (col + 1 < D_) ? bk[col + 1] : 0.f;
        float bv0 = (col < D_) ? bv[col] : 0.f;
        float bv1 = (col + 1 < D_) ? bv[col + 1] : 0.f;
        float k00 = ak[n][0] + bk0, k01 = ak[n][1] + bk1;
        float k10 = ak[n][2] + bk0, k11 = ak[n][3] + bk1;
        ss0 += k00 * k00 + k01 * k01;
        ss1 += k10 * k10 + k11 * k11;
        *(float2*)(g_k + rowg * DP_ + col)       = make_float2(k00, k01);
        *(float2*)(g_k + (rowg + 8) * DP_ + col) = make_float2(k10, k11);
        *(float2*)(g_v + rowg * DP_ + col)       = make_float2(av[n][0] + bv0, av[n][1] + bv1);
        *(float2*)(g_v + (rowg + 8) * DP_ + col) = make_float2(av[n][2] + bv0, av[n][3] + bv1);
    }
    ss0 += __shfl_xor_sync(0xffffffffu, ss0, 1, 4);
    ss0 += __shfl_xor_sync(0xffffffffu, ss0, 2, 4);
    ss1 += __shfl_xor_sync(0xffffffffu, ss1, 1, 4);
    ss1 += __shfl_xor_sync(0xffffffffu, ss1, 2, 4);
    if (t == 0) {
        g_rkn[rowg]     = rsqrtf(ss0);
        g_rkn[rowg + 8] = rsqrtf(ss1);
    }
}

// =================================================================================
// attn: block = (b, 128 t-rows), 8 warps x 16 t-rows. c-loop 8 chunks of 64.
// Scores + PV via 3xTF32 mma; online softmax in registers per warp-quad.
// =================================================================================
__global__ void __launch_bounds__(256)
attn_kernel(const float* __restrict__ pos_bias) {
    extern __shared__ float sm[];
    float* Qh = sm;                    // 128*68
    float* Ql = Qh + 128 * S68;
    float* Kh = Ql + 128 * S68;        // 64*68
    float* Kl = Kh + 64 * S68;
    float* Vh = Kl + 64 * S68;         // 64*68 (TRANSPOSED: [d][c])
    float* Vl = Vh + 64 * S68;
    float* Ph = Vl + 64 * S68;         // 128*68
    float* Pl = Ph + 128 * S68;
    float* rkn_s = Pl + 128 * S68;     // 64
    float* pb_s  = rkn_s + 64;         // 64

    int b = blockIdx.x >> 2, t0 = (blockIdx.x & 3) * 128;
    int tid = threadIdx.x, warp = tid >> 5, lane = tid & 31, g = lane >> 2, t = lane & 3;
    int rA = warp * 16 + g;

    // stage Q once
    for (int i = tid; i < 128 * 16; i += 256) {
        int r = i >> 4, c4 = (i & 15) * 4;
        float4 v = *(const float4*)(g_q + (size_t)(b * NT_ + t0 + r) * DP_ + c4);
        int bix = r * S68 + c4;
        split_store(Qh, Ql, bix,     v.x); split_store(Qh, Ql, bix + 1, v.y);
        split_store(Qh, Ql, bix + 2, v.z); split_store(Qh, Ql, bix + 3, v.w);
    }
    float rq0 = g_rqn[b * NT_ + t0 + rA];
    float rq1 = g_rqn[b * NT_ + t0 + rA + 8];

    float m0 = -1e30f, m1 = -1e30f, l0 = 0.f, l1 = 0.f;
    float oacc[8][4];
#pragma unroll
    for (int n = 0; n < 8; n++)
#pragma unroll
        for (int m = 0; m < 4; m++) oacc[n][m] = 0.f;

    for (int ci = 0; ci < 8; ci++) {
        int c0 = ci * 64;
        __syncthreads();   // prev chunk mma done (also covers initial Q staging)
        for (int i = tid; i < 64 * 16; i += 256) {
            int r = i >> 4, c4 = (i & 15) * 4;
            float4 kv4 = *(const float4*)(g_k + (size_t)(b * NC_ + c0 + r) * DP_ + c4);
            int bix = r * S68 + c4;
            split_store(Kh, Kl, bix,     kv4.x); split_store(Kh, Kl, bix + 1, kv4.y);
            split_store(Kh, Kl, bix + 2, kv4.z); split_store(Kh, Kl, bix + 3, kv4.w);
            float4 vv4 = *(const float4*)(g_v + (size_t)(b * NC_ + c0 + r) * DP_ + c4);
            split_store(Vh, Vl, (c4 + 0) * S68 + r, vv4.x);   // transposed [d][c]
            split_store(Vh, Vl, (c4 + 1) * S68 + r, vv4.y);
            split_store(Vh, Vl, (c4 + 2) * S68 + r, vv4.z);
            split_store(Vh, Vl, (c4 + 3) * S68 + r, vv4.w);
        }
        if (tid < 64) {
            rkn_s[tid] = g_rkn[b * NC_ + c0 + tid];
            pb_s[tid]  = pos_bias[c0 + tid];
        }
        __syncthreads();

        // ---- scores: S = Q K^T, warp rows rA/rA+8, cols 64 ----
        float sc[8][4];
#pragma unroll
        for (int n = 0; n < 8; n++)
#pragma unroll
            for (int m = 0; m < 4; m++) sc[n][m] = 0.f;
#pragma unroll 1
        for (int kk = 0; kk < 64; kk += 8) {
            LD_A(Qh, Ql, rA * S68, (rA + 8) * S68, kk);
#pragma unroll
            for (int n = 0; n < 8; n++)
                MMA3(sc[n], Kh, Kl, (n * 8 + g) * S68 + kk);
        }

        // ---- scale + bias, row max ----
        float mx0 = -1e30f, mx1 = -1e30f;
#pragma unroll
        for (int n = 0; n < 8; n++) {
            int col = n * 8 + 2 * t;
            float rk0 = rkn_s[col], rk1 = rkn_s[col + 1];
            float pb0 = pb_s[col],  pb1 = pb_s[col + 1];
            sc[n][0] = sc[n][0] * fminf(rq0 * rk0, 1e6f) + pb0;
            sc[n][1] = sc[n][1] * fminf(rq0 * rk1, 1e6f) + pb1;
            sc[n][2] = sc[n][2] * fminf(rq1 * rk0, 1e6f) + pb0;
            sc[n][3] = sc[n][3] * fminf(rq1 * rk1, 1e6f) + pb1;
            mx0 = fmaxf(mx0, fmaxf(sc[n][0], sc[n][1]));
            mx1 = fmaxf(mx1, fmaxf(sc[n][2], sc[n][3]));
        }
        mx0 = fmaxf(mx0, __shfl_xor_sync(0xffffffffu, mx0, 1, 4));
        mx0 = fmaxf(mx0, __shfl_xor_sync(0xffffffffu, mx0, 2, 4));
        mx1 = fmaxf(mx1, __shfl_xor_sync(0xffffffffu, mx1, 1, 4));
        mx1 = fmaxf(mx1, __shfl_xor_sync(0xffffffffu, mx1, 2, 4));

        float mn0 = fmaxf(m0, mx0), mn1 = fmaxf(m1, mx1);
        float al0 = __expf(m0 - mn0), al1 = __expf(m1 - mn1);
        m0 = mn0; m1 = mn1;

        float sum0 = 0.f, sum1 = 0.f;
#pragma unroll
        for (int n = 0; n < 8; n++) {
            sc[n][0] = __expf(sc[n][0] - mn0);
            sc[n][1] = __expf(sc[n][1] - mn0);
            sc[n][2] = __expf(sc[n][2] - mn1);
            sc[n][3] = __expf(sc[n][3] - mn1);
            sum0 += sc[n][0] + sc[n][1];
            sum1 += sc[n][2] + sc[n][3];
        }
        sum0 += __shfl_xor_sync(0xffffffffu, sum0, 1, 4);
        sum0 += __shfl_xor_sync(0xffffffffu, sum0, 2, 4);
        sum1 += __shfl_xor_sync(0xffffffffu, sum1, 1, 4);
        sum1 += __shfl_xor_sync(0xffffffffu, sum1, 2, 4);
        l0 = l0 * al0 + sum0;
        l1 = l1 * al1 + sum1;

        // rescale O, write P (warp-private rows -> syncwarp only)
#pragma unroll
        for (int n = 0; n < 8; n++) {
            oacc[n][0] *= al0; oacc[n][1] *= al0;
            oacc[n][2] *= al1; oacc[n][3] *= al1;
        }
        __syncwarp();
#pragma unroll
        for (int n = 0; n < 8; n++) {
            int col = n * 8 + 2 * t;
            split_store(Ph, Pl, rA * S68 + col,           sc[n][0]);
            split_store(Ph, Pl, rA * S68 + col + 1,       sc[n][1]);
            split_store(Ph, Pl, (rA + 8) * S68 + col,     sc[n][2]);
            split_store(Ph, Pl, (rA + 8) * S68 + col + 1, sc[n][3]);
        }
        __syncwarp();

        // ---- PV: O += P V  (A = P rows, k=c; B = Vt[d][c]) ----
#pragma unroll 1
        for (int kk = 0; kk < 64; kk += 8) {
            LD_A(Ph, Pl, rA * S68, (rA + 8) * S68, kk);
#pragma unroll
            for (int n = 0; n < 8; n++)
                MMA3(oacc[n], Vh, Vl, (n * 8 + g) * S68 + kk);
        }
    }

    // finalize
    float li0 = 1.f / l0, li1 = 1.f / l1;
    size_t rowg = (size_t)(b * NT_ + t0 + rA);
#pragma unroll
    for (int n = 0; n < 8; n++) {
        int col = n * 8 + 2 * t;
        *(float2*)(g_s + rowg * DP_ + col) =
            make_float2(oacc[n][0] * li0, oacc[n][1] * li0);
        *(float2*)(g_s + (rowg + 8) * DP_ + col) =
            make_float2(oacc[n][2] * li1, oacc[n][3] * li1);
    }
}

// =================================================================================
// rproj: out[row][256] = g_s[row][0:60] @ R_w^T + R_b.  Block: 128 rows x 128 cols.
// =================================================================================
__global__ void __launch_bounds__(256)
rproj_kernel(const float* __restrict__ Rw, const float* __restrict__ Rb,
             float* __restrict__ out) {
    extern __shared__ float sm[];
    float* Xh = sm;                    // 128*68
    float* Xl = Xh + 128 * S68;
    float* Wh = Xl + 128 * S68;        // 128*68
    float* Wl = Wh + 128 * S68;

    int row0 = (blockIdx.x >> 1) * 128;
    int oc   = (blockIdx.x & 1) * 128;
    int tid = threadIdx.x, warp = tid >> 5, lane = tid & 31, g = lane >> 2, t = lane & 3;
    int rA = warp * 16 + g;

    for (int i = tid; i < 128 * 16; i += 256) {
        int r = i >> 4, c4 = (i & 15) * 4;
        float4 v = *(const float4*)(g_s + (size_t)(row0 + r) * DP_ + c4);
        int bix = r * S68 + c4;
        split_store(Xh, Xl, bix,     v.x); split_store(Xh, Xl, bix + 1, v.y);
        split_store(Xh, Xl, bix + 2, v.z); split_store(Xh, Xl, bix + 3, v.w);
    }
    for (int i = tid; i < 128 * 64; i += 256) {
        int o = i >> 6, k = i & 63;
        float v = (k < D_) ? Rw[(size_t)(oc + o) * D_ + k] : 0.f;
        split_store(Wh, Wl, o * S68 + k, v);
    }
    __syncthreads();

    float acc[16][4];
#pragma unroll
    for (int n = 0; n < 16; n++)
#pragma unroll
        for (int m = 0; m < 4; m++) acc[n][m] = 0.f;

#pragma unroll 1
    for (int kk = 0; kk < 64; kk += 8) {
        LD_A(Xh, Xl, rA * S68, (rA + 8) * S68, kk);
#pragma unroll
        for (int n = 0; n < 16; n++)
            MMA3(acc[n], Wh, Wl, (n * 8 + g) * S68 + kk);
    }

#pragma unroll
    for (int n = 0; n < 16; n++) {
        int col = n * 8 + 2 * t;
        float b0 = Rb[oc + col], b1 = Rb[oc + col + 1];
        *(float2*)(out + (size_t)(row0 + rA) * EMB_ + oc + col) =
            make_float2(acc[n][0] + b0, acc[n][1] + b1);
        *(float2*)(out + (size_t)(row0 + rA + 8) * EMB_ + oc + col) =
            make_float2(acc[n][2] + b0, acc[n][3] + b1);
    }
}

// =================================================================================
// launch
// =================================================================================
extern "C" void kernel_launch(void* const* d_in, const int* in_sizes, int n_in,
                              void* d_out, int out_size) {
    const int*   titems   = (const int*)  d_in[0];
    const int*   citems   = (const int*)  d_in[1];
    const float* tvec     = (const float*)d_in[2];
    const float* cvec     = (const float*)d_in[3];
    const float* At_w     = (const float*)d_in[4];
    const float* At_b     = (const float*)d_in[5];
    const float* Ac_w     = (const float*)d_in[6];
    const float* Ac_b     = (const float*)d_in[7];
    const float* Bc_w     = (const float*)d_in[8];
    const float* Bc_b     = (const float*)d_in[9];
    const float* pos_bias = (const float*)d_in[10];
    const float* R_w      = (const float*)d_in[11];
    const float* R_b      = (const float*)d_in[12];
    float* out = (float*)d_out;

    const int SMEM_Q    = (128 * 2 + 64 * 2) * S68 * 4;            // 104448
    const int SMEM_KV   = (128 * 2 + 64 * 4) * S68 * 4;            // 139264
    const int SMEM_ATTN = (128 * 4 + 64 * 4) * S68 * 4 + 128 * 4;  // 209408
    const int SMEM_R    = (128 * 4) * S68 * 4;                     // 139264

    cudaFuncSetAttribute((const void*)proj_q_kernel,
                         cudaFuncAttributeMaxDynamicSharedMemorySize, SMEM_Q);
    cudaFuncSetAttribute((const void*)proj_kv_kernel,
                         cudaFuncAttributeMaxDynamicSharedMemorySize, SMEM_KV);
    cudaFuncSetAttribute((const void*)attn_kernel,
                         cudaFuncAttributeMaxDynamicSharedMemorySize, SMEM_ATTN);
    cudaFuncSetAttribute((const void*)rproj_kernel,
                         cudaFuncAttributeMaxDynamicSharedMemorySize, SMEM_R);

    proj_q_kernel <<<512,  256, SMEM_Q>>>(titems, tvec, At_w, At_b);
    proj_kv_kernel<<<512,  256, SMEM_KV>>>(citems, cvec, Ac_w, Ac_b, Bc_w, Bc_b);
    attn_kernel   <<<512,  256, SMEM_ATTN>>>(pos_bias);
    rproj_kernel  <<<1024, 256, SMEM_R>>>(R_w, R_b, out);
}

// round 6
// speedup vs baseline: 1.5336x; 1.2495x over previous
#include <cuda_runtime.h>
#include <cstdint>

#define B_    128
#define NT_   512
#define NC_   512
#define EMB_  256
#define D_    60
#define DP_   64
#define S2    68   // float2 row stride for 64-float rows: 136 floats -> 8g+2t bank spread
#define S2H   36   // float2 row stride for 32-float rows: 72 floats  -> 8g+2t bank spread

// ---------------- scratch (device globals; no allocation allowed) ----------------
__device__ float g_q  [B_*NT_*DP_];
__device__ float g_k  [B_*NC_*DP_];
__device__ float g_v  [B_*NC_*DP_];
__device__ float g_s  [B_*NT_*DP_];
__device__ float g_rqn[B_*NT_];
__device__ float g_rkn[B_*NC_];

// ---------------- tf32 helpers ----------------
__device__ __forceinline__ float tf32r(float x) {
    uint32_t u;
    asm("cvt.rna.tf32.f32 %0, %1;" : "=r"(u) : "f"(x));
    return __uint_as_float(u);
}
__device__ __forceinline__ float2 split2(float x) {
    float h = tf32r(x);
    return make_float2(h, tf32r(x - h));
}
__device__ __forceinline__ uint32_t fu(float x) { return __float_as_uint(x); }

__device__ __forceinline__ void mma8(float c[4], uint32_t a0, uint32_t a1,
                                     uint32_t a2, uint32_t a3,
                                     uint32_t b0, uint32_t b1) {
    asm volatile(
        "mma.sync.aligned.m16n8k8.row.col.f32.tf32.tf32.f32 "
        "{%0,%1,%2,%3},{%4,%5,%6,%7},{%8,%9},{%0,%1,%2,%3};"
        : "+f"(c[0]), "+f"(c[1]), "+f"(c[2]), "+f"(c[3])
        : "r"(a0), "r"(a1), "r"(a2), "r"(a3), "r"(b0), "r"(b1));
}

// A fragment: rows (g, g+8) x k (t, t+4) as interleaved hi/lo float2
#define LD_A2(X2, base0, base1, k)                                    \
    float2 fa0 = (X2)[(base0) + (k) + t];                             \
    float2 fa1 = (X2)[(base1) + (k) + t];                             \
    float2 fa2 = (X2)[(base0) + (k) + t + 4];                         \
    float2 fa3 = (X2)[(base1) + (k) + t + 4];                         \
    uint32_t ah0 = fu(fa0.x), ah1 = fu(fa1.x), ah2 = fu(fa2.x), ah3 = fu(fa3.x); \
    uint32_t al0 = fu(fa0.y), al1 = fu(fa1.y), al2 = fu(fa2.y), al3 = fu(fa3.y);

// 3xTF32: hh + h*lo + lo*h
#define MMA3_F2(acc, B2, off)                                         \
    {                                                                 \
        float2 fb0 = (B2)[(off) + t];                                 \
        float2 fb1 = (B2)[(off) + t + 4];                             \
        mma8(acc, ah0, ah1, ah2, ah3, fu(fb0.x), fu(fb1.x));          \
        mma8(acc, ah0, ah1, ah2, ah3, fu(fb0.y), fu(fb1.y));          \
        mma8(acc, al0, al1, al2, al3, fu(fb0.x), fu(fb1.x));          \
    }

// =================================================================================
// proj_q: q[128rows][64] = gather(tvec,items) @ At_w^T + b, plus 1/|q| row norms.
// =================================================================================
__global__ void __launch_bounds__(256, 2)
proj_q_kernel(const int* __restrict__ items_g, const float* __restrict__ vec,
              const float* __restrict__ W, const float* __restrict__ bias) {
    extern __shared__ float2 sm2[];
    float2* X2 = sm2;              // 128*68
    float2* W2 = X2 + 128 * S2;    // 64*68
    __shared__ int items[128];

    int b = blockIdx.x >> 2, r0 = (blockIdx.x & 3) * 128;
    int tid = threadIdx.x, warp = tid >> 5, lane = tid & 31, g = lane >> 2, t = lane & 3;
    if (tid < 128) items[tid] = items_g[b * NT_ + r0 + tid];

    float acc[8][4];
#pragma unroll
    for (int n = 0; n < 8; n++)
#pragma unroll
        for (int m = 0; m < 4; m++) acc[n][m] = 0.f;

    int rA = warp * 16 + g;
    for (int k0 = 0; k0 < EMB_; k0 += 64) {
        __syncthreads();
        for (int i = tid; i < 128 * 16; i += 256) {
            int r = i >> 4, c4 = (i & 15) * 4;
            float4 v = *(const float4*)(vec + (size_t)items[r] * EMB_ + k0 + c4);
            float2* d = X2 + r * S2 + c4;
            d[0] = split2(v.x); d[1] = split2(v.y); d[2] = split2(v.z); d[3] = split2(v.w);
        }
        for (int i = tid; i < 64 * 16; i += 256) {
            int o = i >> 4, c4 = (i & 15) * 4;
            float4 v = make_float4(0.f, 0.f, 0.f, 0.f);
            if (o < D_) v = *(const float4*)(W + (size_t)o * EMB_ + k0 + c4);
            float2* d = W2 + o * S2 + c4;
            d[0] = split2(v.x); d[1] = split2(v.y); d[2] = split2(v.z); d[3] = split2(v.w);
        }
        __syncthreads();
#pragma unroll 2
        for (int kk = 0; kk < 64; kk += 8) {
            LD_A2(X2, rA * S2, (rA + 8) * S2, kk);
#pragma unroll
            for (int n = 0; n < 8; n++)
                MMA3_F2(acc[n], W2, (n * 8 + g) * S2 + kk);
        }
    }
    float ss0 = 0.f, ss1 = 0.f;
    size_t rowg = (size_t)(b * NT_ + r0 + rA);
#pragma unroll
    for (int n = 0; n < 8; n++) {
        int col = n * 8 + 2 * t;
        float b0 = (col < D_) ? bias[col] : 0.f;
        float b1 = (col + 1 < D_) ? bias[col + 1] : 0.f;
        float v00 = acc[n][0] + b0, v01 = acc[n][1] + b1;
        float v10 = acc[n][2] + b0, v11 = acc[n][3] + b1;
        ss0 += v00 * v00 + v01 * v01;
        ss1 += v10 * v10 + v11 * v11;
        *(float2*)(g_q + rowg * DP_ + col)       = make_float2(v00, v01);
        *(float2*)(g_q + (rowg + 8) * DP_ + col) = make_float2(v10, v11);
    }
    ss0 += __shfl_xor_sync(0xffffffffu, ss0, 1, 4);
    ss0 += __shfl_xor_sync(0xffffffffu, ss0, 2, 4);
    ss1 += __shfl_xor_sync(0xffffffffu, ss1, 1, 4);
    ss1 += __shfl_xor_sync(0xffffffffu, ss1, 2, 4);
    if (t == 0) {
        g_rqn[rowg]     = rsqrtf(ss0);
        g_rqn[rowg + 8] = rsqrtf(ss1);
    }
}

// =================================================================================
// proj_kv: K and V projections sharing one gathered X. k chunked by 32.
// =================================================================================
__global__ void __launch_bounds__(256, 2)
proj_kv_kernel(const int* __restrict__ items_g, const float* __restrict__ vec,
               const float* __restrict__ Wk, const float* __restrict__ bk,
               const float* __restrict__ Wv, const float* __restrict__ bv) {
    extern __shared__ float2 sm2[];
    float2* X2  = sm2;               // 128*36
    float2* Wk2 = X2 + 128 * S2H;    // 64*36
    float2* Wv2 = Wk2 + 64 * S2H;    // 64*36
    __shared__ int items[128];

    int b = blockIdx.x >> 2, r0 = (blockIdx.x & 3) * 128;
    int tid = threadIdx.x, warp = tid >> 5, lane = tid & 31, g = lane >> 2, t = lane & 3;
    if (tid < 128) items[tid] = items_g[b * NC_ + r0 + tid];

    float ak[8][4], av[8][4];
#pragma unroll
    for (int n = 0; n < 8; n++)
#pragma unroll
        for (int m = 0; m < 4; m++) { ak[n][m] = 0.f; av[n][m] = 0.f; }

    int rA = warp * 16 + g;
    for (int k0 = 0; k0 < EMB_; k0 += 32) {
        __syncthreads();
        for (int i = tid; i < 128 * 8; i += 256) {
            int r = i >> 3, c4 = (i & 7) * 4;
            float4 v = *(const float4*)(vec + (size_t)items[r] * EMB_ + k0 + c4);
            float2* d = X2 + r * S2H + c4;
            d[0] = split2(v.x); d[1] = split2(v.y); d[2] = split2(v.z); d[3] = split2(v.w);
        }
        for (int i = tid; i < 64 * 8; i += 256) {
            int o = i >> 3, c4 = (i & 7) * 4;
            float4 vk = make_float4(0.f, 0.f, 0.f, 0.f), vv = vk;
            if (o < D_) {
                vk = *(const float4*)(Wk + (size_t)o * EMB_ + k0 + c4);
                vv = *(const float4*)(Wv + (size_t)o * EMB_ + k0 + c4);
            }
            float2* dk = Wk2 + o * S2H + c4;
            dk[0] = split2(vk.x); dk[1] = split2(vk.y); dk[2] = split2(vk.z); dk[3] = split2(vk.w);
            float2* dv = Wv2 + o * S2H + c4;
            dv[0] = split2(vv.x); dv[1] = split2(vv.y); dv[2] = split2(vv.z); dv[3] = split2(vv.w);
        }
        __syncthreads();
#pragma unroll 2
        for (int kk = 0; kk < 32; kk += 8) {
            LD_A2(X2, rA * S2H, (rA + 8) * S2H, kk);
#pragma unroll
            for (int n = 0; n < 8; n++) {
                MMA3_F2(ak[n], Wk2, (n * 8 + g) * S2H + kk);
                MMA3_F2(av[n], Wv2, (n * 8 + g) * S2H + kk);
            }
        }
    }
    float ss0 = 0.f, ss1 = 0.f;
    size_t rowg = (size_t)(b * NC_ + r0 + rA);
#pragma unroll
    for (int n = 0; n < 8; n++) {
        int col = n * 8 + 2 * t;
        float bk0 = (col < D_) ? bk[col] : 0.f;
        float bk1 = (col + 1 < D_) ? bk[col + 1] : 0.f;
        float bv0 = (col < D_) ? bv[col] : 0.f;
        float bv1 = (col + 1 < D_) ? bv[col + 1] : 0.f;
        float k00 = ak[n][0] + bk0, k01 = ak[n][1] + bk1;
        float k10 = ak[n][2] + bk0, k11 = ak[n][3] + bk1;
        ss0 += k00 * k00 + k01 * k01;
        ss1 += k10 * k10 + k11 * k11;
        *(float2*)(g_k + rowg * DP_ + col)       = make_float2(k00, k01);
        *(float2*)(g_k + (rowg + 8) * DP_ + col) = make_float2(k10, k11);
        *(float2*)(g_v + rowg * DP_ + col)       = make_float2(av[n][0] + bv0, av[n][1] + bv1);
        *(float2*)(g_v + (rowg + 8) * DP_ + col) = make_float2(av[n][2] + bv0, av[n][3] + bv1);
    }
    ss0 += __shfl_xor_sync(0xffffffffu, ss0, 1, 4);
    ss0 += __shfl_xor_sync(0xffffffffu, ss0, 2, 4);
    ss1 += __shfl_xor_sync(0xffffffffu, ss1, 1, 4);
    ss1 += __shfl_xor_sync(0xffffffffu, ss1, 2, 4);
    if (t == 0) {
        g_rkn[rowg]     = rsqrtf(ss0);
        g_rkn[rowg + 8] = rsqrtf(ss1);
    }
}

// =================================================================================
// attn: block = (b, 128 t-rows), 8 warps x 16 rows, c-loop 16 chunks of 32.
// Bounded scores -> max-free softmax. P stays in registers via quad shuffles.
// =================================================================================
__global__ void __launch_bounds__(256, 2)
attn_kernel(const float* __restrict__ pos_bias) {
    extern __shared__ float2 sm2[];
    float2* Q2 = sm2;               // 128*68
    float2* K2 = Q2 + 128 * S2;     // 32*68
    float2* V2 = K2 + 32 * S2;      // 32*68
    float* rkn_s = (float*)(V2 + 32 * S2);   // 32
    float* pb_s  = rkn_s + 32;               // 32

    int b = blockIdx.x >> 2, t0 = (blockIdx.x & 3) * 128;
    int tid = threadIdx.x, warp = tid >> 5, lane = tid & 31, g = lane >> 2, t = lane & 3;
    int rA = warp * 16 + g;

    for (int i = tid; i < 128 * 16; i += 256) {
        int r = i >> 4, c4 = (i & 15) * 4;
        float4 v = *(const float4*)(g_q + (size_t)(b * NT_ + t0 + r) * DP_ + c4);
        float2* d = Q2 + r * S2 + c4;
        d[0] = split2(v.x); d[1] = split2(v.y); d[2] = split2(v.z); d[3] = split2(v.w);
    }
    float rq0 = g_rqn[b * NT_ + t0 + rA];
    float rq1 = g_rqn[b * NT_ + t0 + rA + 8];

    float l0 = 0.f, l1 = 0.f;
    float oacc[8][4];
#pragma unroll
    for (int n = 0; n < 8; n++)
#pragma unroll
        for (int m = 0; m < 4; m++) oacc[n][m] = 0.f;

    for (int ci = 0; ci < 16; ci++) {
        int c0 = ci * 32;
        __syncthreads();
        for (int i = tid; i < 32 * 16; i += 256) {
            int r = i >> 4, c4 = (i & 15) * 4;
            float4 kv4 = *(const float4*)(g_k + (size_t)(b * NC_ + c0 + r) * DP_ + c4);
            float2* dk = K2 + r * S2 + c4;
            dk[0] = split2(kv4.x); dk[1] = split2(kv4.y); dk[2] = split2(kv4.z); dk[3] = split2(kv4.w);
            float4 vv4 = *(const float4*)(g_v + (size_t)(b * NC_ + c0 + r) * DP_ + c4);
            float2* dv = V2 + r * S2 + c4;
            dv[0] = split2(vv4.x); dv[1] = split2(vv4.y); dv[2] = split2(vv4.z); dv[3] = split2(vv4.w);
        }
        if (tid < 32) {
            rkn_s[tid] = g_rkn[b * NC_ + c0 + tid];
            pb_s[tid]  = pos_bias[c0 + tid];
        }
        __syncthreads();

        float sc[4][4];
#pragma unroll
        for (int n = 0; n < 4; n++)
#pragma unroll
            for (int m = 0; m < 4; m++) sc[n][m] = 0.f;
#pragma unroll 2
        for (int kk = 0; kk < 64; kk += 8) {
            LD_A2(Q2, rA * S2, (rA + 8) * S2, kk);
#pragma unroll
            for (int n = 0; n < 4; n++)
                MMA3_F2(sc[n], K2, (n * 8 + g) * S2 + kk);
        }

#pragma unroll
        for (int n = 0; n < 4; n++) {
            int col = n * 8 + 2 * t;
            float rk0 = rkn_s[col], rk1 = rkn_s[col + 1];
            float pb0 = pb_s[col],  pb1 = pb_s[col + 1];
            sc[n][0] = __expf(sc[n][0] * fminf(rq0 * rk0, 1e6f) + pb0);
            sc[n][1] = __expf(sc[n][1] * fminf(rq0 * rk1, 1e6f) + pb1);
            sc[n][2] = __expf(sc[n][2] * fminf(rq1 * rk0, 1e6f) + pb0);
            sc[n][3] = __expf(sc[n][3] * fminf(rq1 * rk1, 1e6f) + pb1);
            l0 += sc[n][0] + sc[n][1];
            l1 += sc[n][2] + sc[n][3];
        }

#pragma unroll
        for (int ks = 0; ks < 4; ks++) {
            int b0s = (lane & 28) | (t >> 1);
            int b1s = b0s + 2;
            float x0 = __shfl_sync(0xffffffffu, sc[ks][0], b0s);
            float x1 = __shfl_sync(0xffffffffu, sc[ks][1], b0s);
            float z0 = __shfl_sync(0xffffffffu, sc[ks][2], b0s);
            float z1 = __shfl_sync(0xffffffffu, sc[ks][3], b0s);
            float x2 = __shfl_sync(0xffffffffu, sc[ks][0], b1s);
            float x3 = __shfl_sync(0xffffffffu, sc[ks][1], b1s);
            float z2 = __shfl_sync(0xffffffffu, sc[ks][2], b1s);
            float z3 = __shfl_sync(0xffffffffu, sc[ks][3], b1s);
            bool odd = (t & 1);
            float pa0 = odd ? x1 : x0;
            float pa1 = odd ? z1 : z0;
            float pa2 = odd ? x3 : x2;
            float pa3 = odd ? z3 : z2;
            float ph0f = tf32r(pa0), ph1f = tf32r(pa1), ph2f = tf32r(pa2), ph3f = tf32r(pa3);
            uint32_t ph0 = fu(ph0f), ph1 = fu(ph1f), ph2 = fu(ph2f), ph3 = fu(ph3f);
            uint32_t pl0 = fu(tf32r(pa0 - ph0f)), pl1 = fu(tf32r(pa1 - ph1f));
            uint32_t pl2 = fu(tf32r(pa2 - ph2f)), pl3 = fu(tf32r(pa3 - ph3f));
#pragma unroll
            for (int n = 0; n < 8; n++) {
                float2 fb0 = V2[(ks * 8 + t) * S2 + n * 8 + g];
                float2 fb1 = V2[(ks * 8 + t + 4) * S2 + n * 8 + g];
                mma8(oacc[n], ph0, ph1, ph2, ph3, fu(fb0.x), fu(fb1.x));
                mma8(oacc[n], ph0, ph1, ph2, ph3, fu(fb0.y), fu(fb1.y));
                mma8(oacc[n], pl0, pl1, pl2, pl3, fu(fb0.x), fu(fb1.x));
            }
        }
    }

    l0 += __shfl_xor_sync(0xffffffffu, l0, 1, 4);
    l0 += __shfl_xor_sync(0xffffffffu, l0, 2, 4);
    l1 += __shfl_xor_sync(0xffffffffu, l1, 1, 4);
    l1 += __shfl_xor_sync(0xffffffffu, l1, 2, 4);
    float li0 = 1.f / l0, li1 = 1.f / l1;
    size_t rowg = (size_t)(b * NT_ + t0 + rA);
#pragma unroll
    for (int n = 0; n < 8; n++) {
        int col = n * 8 + 2 * t;
        *(float2*)(g_s + rowg * DP_ + col) =
            make_float2(oacc[n][0] * li0, oacc[n][1] * li0);
        *(float2*)(g_s + (rowg + 8) * DP_ + col) =
            make_float2(oacc[n][2] * li1, oacc[n][3] * li1);
    }
}

// =================================================================================
// rproj: out[row][256] = g_s[row][0:60] @ R_w^T + R_b. Block 128 rows x 64 cols.
// =================================================================================
__global__ void __launch_bounds__(256, 2)
rproj_kernel(const float* __restrict__ Rw, const float* __restrict__ Rb,
             float* __restrict__ out) {
    extern __shared__ float2 sm2[];
    float2* X2 = sm2;              // 128*68
    float2* W2 = X2 + 128 * S2;    // 64*68

    int row0 = (blockIdx.x >> 2) * 128;
    int oc   = (blockIdx.x & 3) * 64;
    int tid = threadIdx.x, warp = tid >> 5, lane = tid & 31, g = lane >> 2, t = lane & 3;
    int rA = warp * 16 + g;

    for (int i = tid; i < 128 * 16; i += 256) {
        int r = i >> 4, c4 = (i & 15) * 4;
        float4 v = *(const float4*)(g_s + (size_t)(row0 + r) * DP_ + c4);
        float2* d = X2 + r * S2 + c4;
        d[0] = split2(v.x); d[1] = split2(v.y); d[2] = split2(v.z); d[3] = split2(v.w);
    }
    for (int i = tid; i < 64 * 16; i += 256) {
        int o = i >> 4, c4 = (i & 15) * 4;
        float4 v = make_float4(0.f, 0.f, 0.f, 0.f);
        if (c4 < D_) v = *(const float4*)(Rw + (size_t)(oc + o) * D_ + c4);
        float2* d = W2 + o * S2 + c4;
        d[0] = split2(v.x); d[1] = split2(v.y); d[2] = split2(v.z); d[3] = split2(v.w);
    }
    __syncthreads();

    float acc[8][4];
#pragma unroll
    for (int n = 0; n < 8; n++)
#pragma unroll
        for (int m = 0; m < 4; m++) acc[n][m] = 0.f;

#pragma unroll 2
    for (int kk = 0; kk < 64; kk += 8) {
        LD_A2(X2, rA * S2, (rA + 8) * S2, kk);
#pragma unroll
        for (int n = 0; n < 8; n++)
            MMA3_F2(acc[n], W2, (n * 8 + g) * S2 + kk);
    }

#pragma unroll
    for (int n = 0; n < 8; n++) {
        int col = n * 8 + 2 * t;
        float b0 = Rb[oc + col], b1 = Rb[oc + col + 1];
        *(float2*)(out + (size_t)(row0 + rA) * EMB_ + oc + col) =
            make_float2(acc[n][0] + b0, acc[n][1] + b1);
        *(float2*)(out + (size_t)(row0 + rA + 8) * EMB_ + oc + col) =
            make_float2(acc[n][2] + b0, acc[n][3] + b1);
    }
}

// =================================================================================
// launch
// =================================================================================
extern "C" void kernel_launch(void* const* d_in, const int* in_sizes, int n_in,
                              void* d_out, int out_size) {
    const int*   titems   = (const int*)  d_in[0];
    const int*   citems   = (const int*)  d_in[1];
    const float* tvec     = (const float*)d_in[2];
    const float* cvec     = (const float*)d_in[3];
    const float* At_w     = (const float*)d_in[4];
    const float* At_b     = (const float*)d_in[5];
    const float* Ac_w     = (const float*)d_in[6];
    const float* Ac_b     = (const float*)d_in[7];
    const float* Bc_w     = (const float*)d_in[8];
    const float* Bc_b     = (const float*)d_in[9];
    const float* pos_bias = (const float*)d_in[10];
    const float* R_w      = (const float*)d_in[11];
    const float* R_b      = (const float*)d_in[12];
    float* out = (float*)d_out;

    const int SMEM_Q    = (128 + 64) * S2 * 8;              // 104448
    const int SMEM_KV   = (128 + 64 + 64) * S2H * 8;        // 73728
    const int SMEM_ATTN = (128 + 32 + 32) * S2 * 8 + 256;   // 104704
    const int SMEM_R    = (128 + 64) * S2 * 8;              // 104448

    cudaFuncSetAttribute((const void*)proj_q_kernel,
                         cudaFuncAttributeMaxDynamicSharedMemorySize, SMEM_Q);
    cudaFuncSetAttribute((const void*)proj_kv_kernel,
                         cudaFuncAttributeMaxDynamicSharedMemorySize, SMEM_KV);
    cudaFuncSetAttribute((const void*)attn_kernel,
                         cudaFuncAttributeMaxDynamicSharedMemorySize, SMEM_ATTN);
    cudaFuncSetAttribute((const void*)rproj_kernel,
                         cudaFuncAttributeMaxDynamicSharedMemorySize, SMEM_R);

    proj_q_kernel <<<512,  256, SMEM_Q>>>(titems, tvec, At_w, At_b);
    proj_kv_kernel<<<512,  256, SMEM_KV>>>(citems, cvec, Ac_w, Ac_b, Bc_w, Bc_b);
    attn_kernel   <<<512,  256, SMEM_ATTN>>>(pos_bias);
    rproj_kernel  <<<2048, 256, SMEM_R>>>(R_w, R_b, out);
}